// round 5
// baseline (speedup 1.0000x reference)
#include <cuda_runtime.h>

// Problem constants
#define BB 32
#define TT 24
#define NN 325
#define DD 64
#define NHEAD 8
#define DHEAD 8

#define NB 8                  // nodes per CTA
#define MROWS (NB * TT)       // 192 rows
#define NTILES ((NN + NB - 1) / NB)   // 41
#define NTHREADS 256

// smem float offsets
#define XB_OFF 0                      // 192*64 (X -> attention O)
#define QB_OFF 12288                  // Q -> FC1 hidden H
#define KB_OFF 24576
#define VB_OFF 36864
#define W0_OFF 49152                  // k-pair-interleaved weight slot 0
#define W1_OFF 53248                  // slot 1
#define SMEM_FLOATS 57344
#define SMEM_BYTES (SMEM_FLOATS * 4)  // 229376 B -> 1 CTA/SM

typedef unsigned long long ull;

__device__ __forceinline__ ull ffma2(ull a, ull b, ull c) {
    ull d;
    asm("fma.rn.f32x2 %0, %1, %2, %3;" : "=l"(d) : "l"(a), "l"(b), "l"(c));
    return d;
}
__device__ __forceinline__ float2 unpack2(ull v) {
    float2 r;
    asm("mov.b64 {%0, %1}, %2;" : "=f"(r.x), "=f"(r.y) : "l"(v));
    return r;
}

// XOR-swizzled row-major offset (64 floats/row = 16 chunks of 4 floats);
// chunk XORed with (row>>3)&7 so rows 8 apart hit distinct banks.
__device__ __forceinline__ int swz4(int r, int k4) {
    return r * DD + (((k4) ^ ((r >> 3) & 7)) << 2);
}

// ---------------------------------------------------------------------------
// Stage a 64x64 weight matrix in k-pair-interleaved form:
// Wp[p*128 + c*2 + {0,1}] = { W[2p][c], W[2p+1][c] }, p = 0..31.
// ---------------------------------------------------------------------------
__device__ __forceinline__ void load_weight_pairs(float* __restrict__ Wp,
                                                  const float* __restrict__ Wg,
                                                  int tid) {
#pragma unroll
    for (int it = 0; it < 2; ++it) {
        int idx = tid + it * NTHREADS;        // 512 tasks
        int p = idx >> 4;
        int c = (idx & 15) * 4;
        float4 g0 = *(const float4*)(Wg + (2 * p) * DD + c);
        float4 g1 = *(const float4*)(Wg + (2 * p + 1) * DD + c);
        float* dst = Wp + p * 128 + c * 2;
        *(float4*)(dst)     = make_float4(g0.x, g1.x, g0.y, g1.y);
        *(float4*)(dst + 4) = make_float4(g0.z, g1.z, g0.w, g1.w);
    }
}

// ---------------------------------------------------------------------------
// GEMM core: C[192x64] = A[192x64] @ W[64x64].
// A: swizzled row-major smem. W: k-pair-interleaved smem.
// Thread tile 6 rows x 8 cols; 32 row-groups x 8 col-groups = 256 threads.
// acc[i][j] packs {sum over even k, sum over odd k}; final = lo + hi.
// ---------------------------------------------------------------------------
__device__ __forceinline__ void gemm_core(const float* __restrict__ As,
                                          const float* __restrict__ Wp,
                                          ull acc[6][8], int r0, int c0) {
#pragma unroll
    for (int i = 0; i < 6; ++i)
#pragma unroll
        for (int j = 0; j < 8; ++j) acc[i][j] = 0ull;

#pragma unroll 2
    for (int kk = 0; kk < 64; kk += 4) {
        const float* wp0 = Wp + (kk >> 1) * 128 + c0 * 2;
        ulonglong2 w0a = *(const ulonglong2*)(wp0);
        ulonglong2 w0b = *(const ulonglong2*)(wp0 + 4);
        ulonglong2 w0c = *(const ulonglong2*)(wp0 + 8);
        ulonglong2 w0d = *(const ulonglong2*)(wp0 + 12);
        ulonglong2 w1a = *(const ulonglong2*)(wp0 + 128);
        ulonglong2 w1b = *(const ulonglong2*)(wp0 + 132);
        ulonglong2 w1c = *(const ulonglong2*)(wp0 + 136);
        ulonglong2 w1d = *(const ulonglong2*)(wp0 + 140);
#pragma unroll
        for (int i = 0; i < 6; ++i) {
            ulonglong2 a = *(const ulonglong2*)(As + swz4(r0 + i, kk >> 2));
            // a.x = {x[kk], x[kk+1]}, a.y = {x[kk+2], x[kk+3]}
            acc[i][0] = ffma2(a.x, w0a.x, acc[i][0]);
            acc[i][1] = ffma2(a.x, w0a.y, acc[i][1]);
            acc[i][2] = ffma2(a.x, w0b.x, acc[i][2]);
            acc[i][3] = ffma2(a.x, w0b.y, acc[i][3]);
            acc[i][4] = ffma2(a.x, w0c.x, acc[i][4]);
            acc[i][5] = ffma2(a.x, w0c.y, acc[i][5]);
            acc[i][6] = ffma2(a.x, w0d.x, acc[i][6]);
            acc[i][7] = ffma2(a.x, w0d.y, acc[i][7]);
            acc[i][0] = ffma2(a.y, w1a.x, acc[i][0]);
            acc[i][1] = ffma2(a.y, w1a.y, acc[i][1]);
            acc[i][2] = ffma2(a.y, w1b.x, acc[i][2]);
            acc[i][3] = ffma2(a.y, w1b.y, acc[i][3]);
            acc[i][4] = ffma2(a.y, w1c.x, acc[i][4]);
            acc[i][5] = ffma2(a.y, w1c.y, acc[i][5]);
            acc[i][6] = ffma2(a.y, w1d.x, acc[i][6]);
            acc[i][7] = ffma2(a.y, w1d.y, acc[i][7]);
        }
    }
}

// Epilogue -> swizzled smem buffer, bias + ReLU.
__device__ __forceinline__ void gemm_to_smem(const float* __restrict__ As,
                                             const float* __restrict__ Wp,
                                             const float* __restrict__ bias,
                                             float* __restrict__ outs, int tid) {
    const int r0 = (tid >> 3) * 6;
    const int c0 = (tid & 7) * 8;
    ull acc[6][8];
    gemm_core(As, Wp, acc, r0, c0);
    float4 b0 = *(const float4*)(bias + c0);
    float4 b1 = *(const float4*)(bias + c0 + 4);
#pragma unroll
    for (int i = 0; i < 6; ++i) {
        float2 s[8];
#pragma unroll
        for (int j = 0; j < 8; ++j) s[j] = unpack2(acc[i][j]);
        float4 r0v, r1v;
        r0v.x = fmaxf(s[0].x + s[0].y + b0.x, 0.f);
        r0v.y = fmaxf(s[1].x + s[1].y + b0.y, 0.f);
        r0v.z = fmaxf(s[2].x + s[2].y + b0.z, 0.f);
        r0v.w = fmaxf(s[3].x + s[3].y + b0.w, 0.f);
        r1v.x = fmaxf(s[4].x + s[4].y + b1.x, 0.f);
        r1v.y = fmaxf(s[5].x + s[5].y + b1.y, 0.f);
        r1v.z = fmaxf(s[6].x + s[6].y + b1.z, 0.f);
        r1v.w = fmaxf(s[7].x + s[7].y + b1.w, 0.f);
        *(float4*)(outs + swz4(r0 + i, c0 >> 2)) = r0v;
        *(float4*)(outs + swz4(r0 + i, (c0 >> 2) + 1)) = r1v;
    }
}

// Epilogue -> global Y (final layer), bias, no ReLU, node guard.
__device__ __forceinline__ void gemm_to_global(const float* __restrict__ As,
                                               const float* __restrict__ Wp,
                                               const float* __restrict__ bias,
                                               float* __restrict__ Y,
                                               int b, int n0, int tid) {
    const int r0 = (tid >> 3) * 6;
    const int c0 = (tid & 7) * 8;
    ull acc[6][8];
    gemm_core(As, Wp, acc, r0, c0);
    float4 b0 = *(const float4*)(bias + c0);
    float4 b1 = *(const float4*)(bias + c0 + 4);
#pragma unroll
    for (int i = 0; i < 6; ++i) {
        int row = r0 + i;
        int node = row / TT;
        int t = row - node * TT;
        int n = n0 + node;
        if (n < NN) {
            float2 s[8];
#pragma unroll
            for (int j = 0; j < 8; ++j) s[j] = unpack2(acc[i][j]);
            float4 r0v = make_float4(s[0].x + s[0].y + b0.x, s[1].x + s[1].y + b0.y,
                                     s[2].x + s[2].y + b0.z, s[3].x + s[3].y + b0.w);
            float4 r1v = make_float4(s[4].x + s[4].y + b1.x, s[5].x + s[5].y + b1.y,
                                     s[6].x + s[6].y + b1.z, s[7].x + s[7].y + b1.w);
            float* dst = Y + ((size_t)(b * TT + t) * NN + n) * DD + c0;
            *(float4*)(dst) = r0v;
            *(float4*)(dst + 4) = r1v;
        }
    }
}

// ---------------------------------------------------------------------------
// Attention: one thread per (node, head, t-sextet). Each K/V row is loaded
// ONCE and used for 6 query rows (6x fewer smem loads than per-t threading).
// No max-subtraction: scores are O(0.1); softmax is shift-invariant and the
// masked entries contribute exactly 0 either way.
// 256 tasks = NTHREADS exactly: node(8) x head(8) x tgroup(4).
// ---------------------------------------------------------------------------
__device__ __forceinline__ void attention(const float* __restrict__ Qs,
                                          const float* __restrict__ Ks,
                                          const float* __restrict__ Vs,
                                          float* __restrict__ Os,
                                          int tid) {
    const float scale = 0.3535533905932738f;  // 1/sqrt(8)
    const int node = tid >> 5;
    const int h = (tid >> 2) & 7;
    const int tg = tid & 3;
    const int tbase = tg * 6;
    const int rbase = node * TT;
    const int ch = 2 * h;

    float q[6][8];
    float o[6][8];
    float sum[6];
#pragma unroll
    for (int i = 0; i < 6; ++i) {
        int row = rbase + tbase + i;
        float4 a = *(const float4*)(Qs + swz4(row, ch));
        float4 c = *(const float4*)(Qs + swz4(row, ch + 1));
        q[i][0] = a.x * scale; q[i][1] = a.y * scale;
        q[i][2] = a.z * scale; q[i][3] = a.w * scale;
        q[i][4] = c.x * scale; q[i][5] = c.y * scale;
        q[i][6] = c.z * scale; q[i][7] = c.w * scale;
        sum[i] = 0.0f;
#pragma unroll
        for (int j = 0; j < 8; ++j) o[i][j] = 0.0f;
    }

#pragma unroll 4
    for (int s = 0; s < TT; ++s) {
        int row = rbase + s;
        float4 k0 = *(const float4*)(Ks + swz4(row, ch));
        float4 k1 = *(const float4*)(Ks + swz4(row, ch + 1));
        float4 v0 = *(const float4*)(Vs + swz4(row, ch));
        float4 v1 = *(const float4*)(Vs + swz4(row, ch + 1));
#pragma unroll
        for (int i = 0; i < 6; ++i) {
            float dot = q[i][0] * k0.x;
            dot = fmaf(q[i][1], k0.y, dot);
            dot = fmaf(q[i][2], k0.z, dot);
            dot = fmaf(q[i][3], k0.w, dot);
            dot = fmaf(q[i][4], k1.x, dot);
            dot = fmaf(q[i][5], k1.y, dot);
            dot = fmaf(q[i][6], k1.z, dot);
            dot = fmaf(q[i][7], k1.w, dot);
            float e = (s >= tbase + i) ? __expf(dot) : 0.0f;
            sum[i] += e;
            o[i][0] = fmaf(e, v0.x, o[i][0]);
            o[i][1] = fmaf(e, v0.y, o[i][1]);
            o[i][2] = fmaf(e, v0.z, o[i][2]);
            o[i][3] = fmaf(e, v0.w, o[i][3]);
            o[i][4] = fmaf(e, v1.x, o[i][4]);
            o[i][5] = fmaf(e, v1.y, o[i][5]);
            o[i][6] = fmaf(e, v1.z, o[i][6]);
            o[i][7] = fmaf(e, v1.w, o[i][7]);
        }
    }

#pragma unroll
    for (int i = 0; i < 6; ++i) {
        float inv = 1.0f / sum[i];
        int row = rbase + tbase + i;
        *(float4*)(Os + swz4(row, ch)) =
            make_float4(o[i][0] * inv, o[i][1] * inv, o[i][2] * inv, o[i][3] * inv);
        *(float4*)(Os + swz4(row, ch + 1)) =
            make_float4(o[i][4] * inv, o[i][5] * inv, o[i][6] * inv, o[i][7] * inv);
    }
}

// ---------------------------------------------------------------------------
// Fused kernel: one CTA per (batch, 8-node tile).
// ---------------------------------------------------------------------------
__global__ void __launch_bounds__(NTHREADS, 1)
temporal_attention_fused(const float* __restrict__ X,
                         const float* __restrict__ Wq, const float* __restrict__ bq,
                         const float* __restrict__ Wk, const float* __restrict__ bk,
                         const float* __restrict__ Wv, const float* __restrict__ bv,
                         const float* __restrict__ Wf1, const float* __restrict__ bf1,
                         const float* __restrict__ Wf2, const float* __restrict__ bf2,
                         float* __restrict__ Y) {
    extern __shared__ float smem[];
    float* Xb = smem + XB_OFF;   // X, later attention output O
    float* Qb = smem + QB_OFF;   // Q, later FC1 hidden H
    float* Kb = smem + KB_OFF;
    float* Vb = smem + VB_OFF;
    float* W0 = smem + W0_OFF;
    float* W1 = smem + W1_OFF;

    const int tid = threadIdx.x;
    const int n0 = blockIdx.x * NB;
    const int b = blockIdx.y;

    // Load X tile into swizzled layout; zero-fill out-of-range nodes.
#pragma unroll 2
    for (int i = tid; i < MROWS * 16; i += NTHREADS) {
        int row = i >> 4;
        int f4 = i & 15;
        int node = row / TT;
        int t = row - node * TT;
        int n = n0 + node;
        float4 v = make_float4(0.f, 0.f, 0.f, 0.f);
        if (n < NN)
            v = *(const float4*)(X + ((size_t)(b * TT + t) * NN + n) * DD + f4 * 4);
        *(float4*)(Xb + swz4(row, f4)) = v;
    }
    load_weight_pairs(W0, Wq, tid);
    __syncthreads();

    load_weight_pairs(W1, Wk, tid);           // overlap with Q GEMM
    gemm_to_smem(Xb, W0, bq, Qb, tid);        // q = relu(X@Wq + bq)
    __syncthreads();

    load_weight_pairs(W0, Wv, tid);
    gemm_to_smem(Xb, W1, bk, Kb, tid);        // k
    __syncthreads();

    load_weight_pairs(W1, Wf1, tid);
    gemm_to_smem(Xb, W0, bv, Vb, tid);        // v
    __syncthreads();

    attention(Qb, Kb, Vb, Xb, tid);           // O overwrites X buffer
    __syncthreads();

    load_weight_pairs(W0, Wf2, tid);
    gemm_to_smem(Xb, W1, bf1, Qb, tid);       // h = relu(O@Wf1 + bf1) -> Q buffer
    __syncthreads();

    gemm_to_global(Qb, W0, bf2, Y, b, n0, tid);  // y = h@Wf2 + bf2
}

// ---------------------------------------------------------------------------
// kernel_launch: inputs per metadata order:
// 0=X 1=STE(unused) 2=Wq 3=bq 4=Wk 5=bk 6=Wv 7=bv 8=Wf1 9=bf1 10=Wf2 11=bf2
// ---------------------------------------------------------------------------
extern "C" void kernel_launch(void* const* d_in, const int* in_sizes, int n_in,
                              void* d_out, int out_size) {
    const float* X   = (const float*)d_in[0];
    const float* Wq  = (const float*)d_in[2];
    const float* bq  = (const float*)d_in[3];
    const float* Wk  = (const float*)d_in[4];
    const float* bk  = (const float*)d_in[5];
    const float* Wv  = (const float*)d_in[6];
    const float* bv  = (const float*)d_in[7];
    const float* Wf1 = (const float*)d_in[8];
    const float* bf1 = (const float*)d_in[9];
    const float* Wf2 = (const float*)d_in[10];
    const float* bf2 = (const float*)d_in[11];
    float* Y = (float*)d_out;

    cudaFuncSetAttribute(temporal_attention_fused,
                         cudaFuncAttributeMaxDynamicSharedMemorySize, SMEM_BYTES);

    dim3 grid(NTILES, BB);
    temporal_attention_fused<<<grid, NTHREADS, SMEM_BYTES>>>(
        X, Wq, bq, Wk, bk, Wv, bv, Wf1, bf1, Wf2, bf2, Y);
}

// round 6
// speedup vs baseline: 1.7021x; 1.7021x over previous
#include <cuda_runtime.h>

// Problem constants
#define BB 32
#define TT 24
#define NN 325
#define DD 64
#define NHEAD 8
#define DHEAD 8

#define NB 4                  // nodes per CTA
#define MROWS (NB * TT)       // 96 rows
#define NTILES ((NN + NB - 1) / NB)   // 82
#define NTHREADS 256

// smem float offsets (R1 footprint: 114688 B -> 2 CTAs/SM)
#define XB_OFF 0                      // 96*64 = 6144 (X -> attention O)
#define QB_OFF 6144                   // Q -> FC1 hidden H
#define KB_OFF 12288
#define VB_OFF 18432
#define WP_OFF 24576                  // split-pair weight slot (4096 floats)
#define SMEM_FLOATS 28672
#define SMEM_BYTES (SMEM_FLOATS * 4)  // 114688

typedef unsigned long long ull;

__device__ __forceinline__ ull ffma2(ull a, ull b, ull c) {
    ull d;
    asm("fma.rn.f32x2 %0, %1, %2, %3;" : "=l"(d) : "l"(a), "l"(b), "l"(c));
    return d;
}
__device__ __forceinline__ float2 unpack2(ull v) {
    float2 r;
    asm("mov.b64 {%0, %1}, %2;" : "=f"(r.x), "=f"(r.y) : "l"(v));
    return r;
}

// XOR-swizzled row-major offset: 64 floats/row = 16 chunks of 4 floats.
// chunk ^= (row & 7): rows 2,4,6 apart map to distinct banks.
__device__ __forceinline__ int swz4(int r, int k4) {
    return r * DD + (((k4) ^ (r & 7)) << 2);
}

// ---------------------------------------------------------------------------
// Stage a 64x64 weight matrix into split-pair form. For k-pair p (0..31) and
// column-chunk cg (0..15):
//   Wp[p*128 +      cg*4 + {0..3}] = {W[2p][4cg],   W[2p+1][4cg],
//                                     W[2p][4cg+1], W[2p+1][4cg+1]}
//   Wp[p*128 + 64 + cg*4 + {0..3}] = {W[2p][4cg+2], W[2p+1][4cg+2],
//                                     W[2p][4cg+3], W[2p+1][4cg+3]}
// Per-warp GEMM reads of 16 cg's are then 256 B contiguous -> conflict-free.
// ---------------------------------------------------------------------------
__device__ __forceinline__ void load_weight_pairs(float* __restrict__ Wp,
                                                  const float* __restrict__ Wg,
                                                  int tid) {
#pragma unroll
    for (int it = 0; it < 2; ++it) {
        int idx = tid + it * NTHREADS;        // 512 tasks: p(32) x cg(16)
        int p = idx >> 4;
        int cg = idx & 15;
        float4 g0 = *(const float4*)(Wg + (2 * p) * DD + cg * 4);
        float4 g1 = *(const float4*)(Wg + (2 * p + 1) * DD + cg * 4);
        float* dst = Wp + p * 128 + cg * 4;
        *(float4*)(dst)      = make_float4(g0.x, g1.x, g0.y, g1.y);
        *(float4*)(dst + 64) = make_float4(g0.z, g1.z, g0.w, g1.w);
    }
}

// ---------------------------------------------------------------------------
// GEMM core: C[96x64] = A[96x64] @ W[64x64].
// Thread tile 6 rows x 4 cols; 16 row-groups x 16 col-groups = 256 threads.
// acc[i][j] packs {sum over even k, sum over odd k} for column c0+j.
// ---------------------------------------------------------------------------
__device__ __forceinline__ void gemm_core(const float* __restrict__ As,
                                          const float* __restrict__ Wp,
                                          ull acc[6][4], int r0, int cg) {
#pragma unroll
    for (int i = 0; i < 6; ++i)
#pragma unroll
        for (int j = 0; j < 4; ++j) acc[i][j] = 0ull;

#pragma unroll 2
    for (int kk = 0; kk < 64; kk += 4) {
        const float* wb = Wp + (kk >> 1) * 128 + cg * 4;
        ulonglong2 w0lo = *(const ulonglong2*)(wb);         // k kk,kk+1 cols c0,c0+1
        ulonglong2 w0hi = *(const ulonglong2*)(wb + 64);    // k kk,kk+1 cols c0+2,c0+3
        ulonglong2 w1lo = *(const ulonglong2*)(wb + 128);   // k kk+2,kk+3 cols c0,c0+1
        ulonglong2 w1hi = *(const ulonglong2*)(wb + 192);
#pragma unroll
        for (int i = 0; i < 6; ++i) {
            ulonglong2 a = *(const ulonglong2*)(As + swz4(r0 + i, kk >> 2));
            // a.x = {x[kk], x[kk+1]}, a.y = {x[kk+2], x[kk+3]}
            acc[i][0] = ffma2(a.x, w0lo.x, acc[i][0]);
            acc[i][1] = ffma2(a.x, w0lo.y, acc[i][1]);
            acc[i][2] = ffma2(a.x, w0hi.x, acc[i][2]);
            acc[i][3] = ffma2(a.x, w0hi.y, acc[i][3]);
            acc[i][0] = ffma2(a.y, w1lo.x, acc[i][0]);
            acc[i][1] = ffma2(a.y, w1lo.y, acc[i][1]);
            acc[i][2] = ffma2(a.y, w1hi.x, acc[i][2]);
            acc[i][3] = ffma2(a.y, w1hi.y, acc[i][3]);
        }
    }
}

// Epilogue -> swizzled smem buffer, bias + ReLU.
__device__ __forceinline__ void gemm_to_smem(const float* __restrict__ As,
                                             const float* __restrict__ Wp,
                                             const float* __restrict__ bias,
                                             float* __restrict__ outs, int tid) {
    const int r0 = (tid >> 4) * 6;
    const int cg = tid & 15;
    ull acc[6][4];
    gemm_core(As, Wp, acc, r0, cg);
    float4 bb = *(const float4*)(bias + cg * 4);
#pragma unroll
    for (int i = 0; i < 6; ++i) {
        float2 s0 = unpack2(acc[i][0]);
        float2 s1 = unpack2(acc[i][1]);
        float2 s2 = unpack2(acc[i][2]);
        float2 s3 = unpack2(acc[i][3]);
        float4 r;
        r.x = fmaxf(s0.x + s0.y + bb.x, 0.f);
        r.y = fmaxf(s1.x + s1.y + bb.y, 0.f);
        r.z = fmaxf(s2.x + s2.y + bb.z, 0.f);
        r.w = fmaxf(s3.x + s3.y + bb.w, 0.f);
        *(float4*)(outs + swz4(r0 + i, cg)) = r;
    }
}

// Epilogue -> global Y (final layer), bias, no ReLU, node guard.
__device__ __forceinline__ void gemm_to_global(const float* __restrict__ As,
                                               const float* __restrict__ Wp,
                                               const float* __restrict__ bias,
                                               float* __restrict__ Y,
                                               int b, int n0, int tid) {
    const int r0 = (tid >> 4) * 6;
    const int cg = tid & 15;
    ull acc[6][4];
    gemm_core(As, Wp, acc, r0, cg);
    float4 bb = *(const float4*)(bias + cg * 4);
#pragma unroll
    for (int i = 0; i < 6; ++i) {
        int row = r0 + i;
        int node = row / TT;
        int t = row - node * TT;
        int n = n0 + node;
        if (n < NN) {
            float2 s0 = unpack2(acc[i][0]);
            float2 s1 = unpack2(acc[i][1]);
            float2 s2 = unpack2(acc[i][2]);
            float2 s3 = unpack2(acc[i][3]);
            float4 r = make_float4(s0.x + s0.y + bb.x, s1.x + s1.y + bb.y,
                                   s2.x + s2.y + bb.z, s3.x + s3.y + bb.w);
            *(float4*)(Y + ((size_t)(b * TT + t) * NN + n) * DD + cg * 4) = r;
        }
    }
}

// ---------------------------------------------------------------------------
// Attention: one thread per (node, head, t-triple): 4*8*8 = 256 tasks.
// Each K/V row is loaded ONCE per thread and reused for 3 query rows.
// No max-subtraction: scores are O(0.1); softmax is shift-invariant and
// masked entries contribute exactly 0 either way.
// ---------------------------------------------------------------------------
__device__ __forceinline__ void attention(const float* __restrict__ Qs,
                                          const float* __restrict__ Ks,
                                          const float* __restrict__ Vs,
                                          float* __restrict__ Os,
                                          int tid) {
    const float scale = 0.3535533905932738f;  // 1/sqrt(8)
    const int node = tid >> 6;
    const int h = (tid >> 3) & 7;
    const int tg = tid & 7;
    const int tbase = tg * 3;
    const int rbase = node * TT;
    const int ch = 2 * h;

    float q[3][8];
    float o[3][8];
    float sum[3];
#pragma unroll
    for (int i = 0; i < 3; ++i) {
        int row = rbase + tbase + i;
        float4 a = *(const float4*)(Qs + swz4(row, ch));
        float4 c = *(const float4*)(Qs + swz4(row, ch + 1));
        q[i][0] = a.x * scale; q[i][1] = a.y * scale;
        q[i][2] = a.z * scale; q[i][3] = a.w * scale;
        q[i][4] = c.x * scale; q[i][5] = c.y * scale;
        q[i][6] = c.z * scale; q[i][7] = c.w * scale;
        sum[i] = 0.0f;
#pragma unroll
        for (int j = 0; j < 8; ++j) o[i][j] = 0.0f;
    }

#pragma unroll 4
    for (int s = 0; s < TT; ++s) {
        int row = rbase + s;
        float4 k0 = *(const float4*)(Ks + swz4(row, ch));
        float4 k1 = *(const float4*)(Ks + swz4(row, ch + 1));
        float4 v0 = *(const float4*)(Vs + swz4(row, ch));
        float4 v1 = *(const float4*)(Vs + swz4(row, ch + 1));
#pragma unroll
        for (int i = 0; i < 3; ++i) {
            float dot = q[i][0] * k0.x;
            dot = fmaf(q[i][1], k0.y, dot);
            dot = fmaf(q[i][2], k0.z, dot);
            dot = fmaf(q[i][3], k0.w, dot);
            dot = fmaf(q[i][4], k1.x, dot);
            dot = fmaf(q[i][5], k1.y, dot);
            dot = fmaf(q[i][6], k1.z, dot);
            dot = fmaf(q[i][7], k1.w, dot);
            float e = (s >= tbase + i) ? __expf(dot) : 0.0f;
            sum[i] += e;
            o[i][0] = fmaf(e, v0.x, o[i][0]);
            o[i][1] = fmaf(e, v0.y, o[i][1]);
            o[i][2] = fmaf(e, v0.z, o[i][2]);
            o[i][3] = fmaf(e, v0.w, o[i][3]);
            o[i][4] = fmaf(e, v1.x, o[i][4]);
            o[i][5] = fmaf(e, v1.y, o[i][5]);
            o[i][6] = fmaf(e, v1.z, o[i][6]);
            o[i][7] = fmaf(e, v1.w, o[i][7]);
        }
    }

#pragma unroll
    for (int i = 0; i < 3; ++i) {
        float inv = 1.0f / sum[i];
        int row = rbase + tbase + i;
        *(float4*)(Os + swz4(row, ch)) =
            make_float4(o[i][0] * inv, o[i][1] * inv, o[i][2] * inv, o[i][3] * inv);
        *(float4*)(Os + swz4(row, ch + 1)) =
            make_float4(o[i][4] * inv, o[i][5] * inv, o[i][6] * inv, o[i][7] * inv);
    }
}

// ---------------------------------------------------------------------------
// Fused kernel: one CTA per (batch, 4-node tile); 2 CTAs/SM.
// ---------------------------------------------------------------------------
__global__ void __launch_bounds__(NTHREADS, 2)
temporal_attention_fused(const float* __restrict__ X,
                         const float* __restrict__ Wq, const float* __restrict__ bq,
                         const float* __restrict__ Wk, const float* __restrict__ bk,
                         const float* __restrict__ Wv, const float* __restrict__ bv,
                         const float* __restrict__ Wf1, const float* __restrict__ bf1,
                         const float* __restrict__ Wf2, const float* __restrict__ bf2,
                         float* __restrict__ Y) {
    extern __shared__ float smem[];
    float* Xb = smem + XB_OFF;   // X, later attention output O
    float* Qb = smem + QB_OFF;   // Q, later FC1 hidden H
    float* Kb = smem + KB_OFF;
    float* Vb = smem + VB_OFF;
    float* Wp = smem + WP_OFF;

    const int tid = threadIdx.x;
    const int n0 = blockIdx.x * NB;
    const int b = blockIdx.y;

    // Load X tile into swizzled layout; zero-fill out-of-range nodes.
#pragma unroll 2
    for (int i = tid; i < MROWS * 16; i += NTHREADS) {
        int row = i >> 4;
        int f4 = i & 15;
        int node = row / TT;
        int t = row - node * TT;
        int n = n0 + node;
        float4 v = make_float4(0.f, 0.f, 0.f, 0.f);
        if (n < NN)
            v = *(const float4*)(X + ((size_t)(b * TT + t) * NN + n) * DD + f4 * 4);
        *(float4*)(Xb + swz4(row, f4)) = v;
    }
    load_weight_pairs(Wp, Wq, tid);
    __syncthreads();

    gemm_to_smem(Xb, Wp, bq, Qb, tid);        // q = relu(X@Wq + bq)
    __syncthreads();
    load_weight_pairs(Wp, Wk, tid);
    __syncthreads();
    gemm_to_smem(Xb, Wp, bk, Kb, tid);        // k
    __syncthreads();
    load_weight_pairs(Wp, Wv, tid);
    __syncthreads();
    gemm_to_smem(Xb, Wp, bv, Vb, tid);        // v
    __syncthreads();

    load_weight_pairs(Wp, Wf1, tid);          // stage Wf1 while attention runs
    attention(Qb, Kb, Vb, Xb, tid);           // O overwrites X buffer
    __syncthreads();

    gemm_to_smem(Xb, Wp, bf1, Qb, tid);       // h = relu(O@Wf1 + bf1) -> Q buffer
    __syncthreads();
    load_weight_pairs(Wp, Wf2, tid);
    __syncthreads();
    gemm_to_global(Qb, Wp, bf2, Y, b, n0, tid);  // y = h@Wf2 + bf2
}

// ---------------------------------------------------------------------------
// kernel_launch: inputs per metadata order:
// 0=X 1=STE(unused) 2=Wq 3=bq 4=Wk 5=bk 6=Wv 7=bv 8=Wf1 9=bf1 10=Wf2 11=bf2
// ---------------------------------------------------------------------------
extern "C" void kernel_launch(void* const* d_in, const int* in_sizes, int n_in,
                              void* d_out, int out_size) {
    const float* X   = (const float*)d_in[0];
    const float* Wq  = (const float*)d_in[2];
    const float* bq  = (const float*)d_in[3];
    const float* Wk  = (const float*)d_in[4];
    const float* bk  = (const float*)d_in[5];
    const float* Wv  = (const float*)d_in[6];
    const float* bv  = (const float*)d_in[7];
    const float* Wf1 = (const float*)d_in[8];
    const float* bf1 = (const float*)d_in[9];
    const float* Wf2 = (const float*)d_in[10];
    const float* bf2 = (const float*)d_in[11];
    float* Y = (float*)d_out;

    cudaFuncSetAttribute(temporal_attention_fused,
                         cudaFuncAttributeMaxDynamicSharedMemorySize, SMEM_BYTES);

    dim3 grid(NTILES, BB);
    temporal_attention_fused<<<grid, NTHREADS, SMEM_BYTES>>>(
        X, Wq, bq, Wk, bk, Wv, bv, Wf1, bf1, Wf2, bf2, Y);
}

// round 7
// speedup vs baseline: 1.9562x; 1.1493x over previous
#include <cuda_runtime.h>

// Problem constants
#define BB 32
#define TT 24
#define NN 325
#define DD 64
#define NHEAD 8
#define DHEAD 8

#define NB 4                  // nodes per CTA
#define MROWS (NB * TT)       // 96 rows
#define NTILES ((NN + NB - 1) / NB)   // 82
#define NTHREADS 256

// smem float offsets (114688 B -> 2 CTAs/SM)
#define XB_OFF 0                      // 96*64 (X -> attention O)
#define QB_OFF 6144                   // Q -> FC1 hidden H
#define KB_OFF 12288
#define VB_OFF 18432
#define WP_OFF 24576                  // split-pair weight slot (4096 floats)
#define SMEM_FLOATS 28672
#define SMEM_BYTES (SMEM_FLOATS * 4)

typedef unsigned long long ull;

__device__ __forceinline__ ull ffma2(ull a, ull b, ull c) {
    ull d;
    asm("fma.rn.f32x2 %0, %1, %2, %3;" : "=l"(d) : "l"(a), "l"(b), "l"(c));
    return d;
}
__device__ __forceinline__ float2 unpack2(ull v) {
    float2 r;
    asm("mov.b64 {%0, %1}, %2;" : "=f"(r.x), "=f"(r.y) : "l"(v));
    return r;
}

// Storage swizzle: logical chunk k4 (0..15) of row r lives at memory chunk
// k4 ^ ci(r), with ci(r) = (r/6) & 7  — constant over each GEMM thread's
// 6-row tile, distinct for adjacent row-groups.
__device__ __forceinline__ int ci_of_row(int r) { return (r / 6) & 7; }
__device__ __forceinline__ int swz(int r, int k4) {
    return r * DD + (((k4) ^ ci_of_row(r)) << 2);
}

// ---------------------------------------------------------------------------
// Stage a 64x64 weight matrix into split-pair form. For k-group k4 (0..15),
// pairs p0=2*k4, p1=2*k4+1, column-chunk cg (0..15):
//   block = Wp + k4*256
//   block[cg*4 + {0..3}]        = {W[2p0][c0],W[2p0+1][c0],W[2p0][c1],W[2p0+1][c1]}   (p0 rows, cols 4cg,4cg+1)
//   block[64 + cg*4 + {0..3}]   = cols 4cg+2, 4cg+3 of pair p0
//   block[128 + cg*4 + {0..3}]  = cols 4cg,   4cg+1 of pair p1
//   block[192 + cg*4 + {0..3}]  = cols 4cg+2, 4cg+3 of pair p1
// ---------------------------------------------------------------------------
__device__ __forceinline__ void load_weight_pairs(float* __restrict__ Wp,
                                                  const float* __restrict__ Wg,
                                                  int tid) {
#pragma unroll
    for (int it = 0; it < 2; ++it) {
        int idx = tid + it * NTHREADS;        // 512 tasks: p(32) x cg(16)
        int p = idx >> 4;                     // k-pair index 0..31
        int cg = idx & 15;
        float4 g0 = *(const float4*)(Wg + (2 * p) * DD + cg * 4);
        float4 g1 = *(const float4*)(Wg + (2 * p + 1) * DD + cg * 4);
        int k4 = p >> 1;
        int sub = (p & 1) ? 128 : 0;
        float* dst = Wp + (k4 << 8) + sub + cg * 4;
        *(float4*)(dst)      = make_float4(g0.x, g1.x, g0.y, g1.y);
        *(float4*)(dst + 64) = make_float4(g0.z, g1.z, g0.w, g1.w);
    }
}

// ---------------------------------------------------------------------------
// GEMM core: C[96x64] = A[96x64] @ W[64x64].
// Thread tile 6 rows x 4 cols; 16 row-groups x 16 col-groups = 256 threads.
// A iterated in MEMORY order (linear, zero address ALU); de-swizzle paid on
// the W block index: k4 = mc ^ ci (one XOR per k-step for all 10 loads).
// acc[i][j] packs {even-k sum, odd-k sum}; final = lo + hi.
// ---------------------------------------------------------------------------
__device__ __forceinline__ void gemm_core(const float* __restrict__ As,
                                          const float* __restrict__ Wp,
                                          ull acc[6][4], int r0, int cg, int ci) {
#pragma unroll
    for (int i = 0; i < 6; ++i)
#pragma unroll
        for (int j = 0; j < 4; ++j) acc[i][j] = 0ull;

    const float* a0 = As + r0 * DD;
    const float* wcg = Wp + cg * 4;

#pragma unroll 4
    for (int mc = 0; mc < 16; ++mc) {
        const float* wb = wcg + ((mc ^ ci) << 8);
        ulonglong2 w0lo = *(const ulonglong2*)(wb);         // pair p0, cols 0,1
        ulonglong2 w0hi = *(const ulonglong2*)(wb + 64);    // pair p0, cols 2,3
        ulonglong2 w1lo = *(const ulonglong2*)(wb + 128);   // pair p1, cols 0,1
        ulonglong2 w1hi = *(const ulonglong2*)(wb + 192);   // pair p1, cols 2,3
#pragma unroll
        for (int i = 0; i < 6; ++i) {
            ulonglong2 a = *(const ulonglong2*)(a0 + i * DD + mc * 4);
            // a.x = {x[4k4], x[4k4+1]}, a.y = {x[4k4+2], x[4k4+3]}
            acc[i][0] = ffma2(a.x, w0lo.x, acc[i][0]);
            acc[i][1] = ffma2(a.x, w0lo.y, acc[i][1]);
            acc[i][2] = ffma2(a.x, w0hi.x, acc[i][2]);
            acc[i][3] = ffma2(a.x, w0hi.y, acc[i][3]);
            acc[i][0] = ffma2(a.y, w1lo.x, acc[i][0]);
            acc[i][1] = ffma2(a.y, w1lo.y, acc[i][1]);
            acc[i][2] = ffma2(a.y, w1hi.x, acc[i][2]);
            acc[i][3] = ffma2(a.y, w1hi.y, acc[i][3]);
        }
    }
}

// Epilogue -> swizzled smem buffer, bias + ReLU.
__device__ __forceinline__ void gemm_to_smem(const float* __restrict__ As,
                                             const float* __restrict__ Wp,
                                             const float* __restrict__ bias,
                                             float* __restrict__ outs, int tid) {
    const int rg = tid >> 4;
    const int cg = tid & 15;
    const int r0 = rg * 6;
    const int ci = rg & 7;
    ull acc[6][4];
    gemm_core(As, Wp, acc, r0, cg, ci);
    float4 bb = *(const float4*)(bias + cg * 4);
    const int sc = (cg ^ ci) << 2;           // swizzled store chunk offset
#pragma unroll
    for (int i = 0; i < 6; ++i) {
        float2 s0 = unpack2(acc[i][0]);
        float2 s1 = unpack2(acc[i][1]);
        float2 s2 = unpack2(acc[i][2]);
        float2 s3 = unpack2(acc[i][3]);
        float4 r;
        r.x = fmaxf(s0.x + s0.y + bb.x, 0.f);
        r.y = fmaxf(s1.x + s1.y + bb.y, 0.f);
        r.z = fmaxf(s2.x + s2.y + bb.z, 0.f);
        r.w = fmaxf(s3.x + s3.y + bb.w, 0.f);
        *(float4*)(outs + (r0 + i) * DD + sc) = r;
    }
}

// Epilogue -> global Y (final layer), bias, no ReLU, node guard.
__device__ __forceinline__ void gemm_to_global(const float* __restrict__ As,
                                               const float* __restrict__ Wp,
                                               const float* __restrict__ bias,
                                               float* __restrict__ Y,
                                               int b, int n0, int tid) {
    const int rg = tid >> 4;
    const int cg = tid & 15;
    const int r0 = rg * 6;
    const int ci = rg & 7;
    ull acc[6][4];
    gemm_core(As, Wp, acc, r0, cg, ci);
    float4 bb = *(const float4*)(bias + cg * 4);
#pragma unroll
    for (int i = 0; i < 6; ++i) {
        int row = r0 + i;
        int node = row / TT;
        int t = row - node * TT;
        int n = n0 + node;
        if (n < NN) {
            float2 s0 = unpack2(acc[i][0]);
            float2 s1 = unpack2(acc[i][1]);
            float2 s2 = unpack2(acc[i][2]);
            float2 s3 = unpack2(acc[i][3]);
            float4 r = make_float4(s0.x + s0.y + bb.x, s1.x + s1.y + bb.y,
                                   s2.x + s2.y + bb.z, s3.x + s3.y + bb.w);
            *(float4*)(Y + ((size_t)(b * TT + t) * NN + n) * DD + cg * 4) = r;
        }
    }
}

// ---------------------------------------------------------------------------
// Attention: one thread per (node, head, t-triple): 4*8*8 = 256 tasks.
// K/V rows loaded once per 3 queries. s-loop split 4x6 so s/6 = j is
// compile-time: swizzle chunk offsets computed once per 6 steps.
// No max-subtraction (softmax shift-invariant; masked terms exactly 0).
// ---------------------------------------------------------------------------
__device__ __forceinline__ void attention(const float* __restrict__ Qs,
                                          const float* __restrict__ Ks,
                                          const float* __restrict__ Vs,
                                          float* __restrict__ Os,
                                          int tid) {
    const float scale = 0.3535533905932738f;  // 1/sqrt(8)
    const int node = tid >> 6;
    const int h = (tid >> 3) & 7;
    const int tg = tid & 7;
    const int tbase = tg * 3;
    const int rbase = node * TT;
    const int ch = 2 * h;

    // Q rows rbase + tg*3 + {0,1,2} all share ci = (node*4 + (tg>>1)) & 7
    const int ciq = ((node << 2) + (tg >> 1)) & 7;
    const int qc1 = ((ch ^ ciq) << 2);
    const int qc2 = (((ch + 1) ^ ciq) << 2);

    float q[3][8];
    float o[3][8];
    float sum[3];
#pragma unroll
    for (int i = 0; i < 3; ++i) {
        const float* qr = Qs + (rbase + tbase + i) * DD;
        float4 a = *(const float4*)(qr + qc1);
        float4 c = *(const float4*)(qr + qc2);
        q[i][0] = a.x * scale; q[i][1] = a.y * scale;
        q[i][2] = a.z * scale; q[i][3] = a.w * scale;
        q[i][4] = c.x * scale; q[i][5] = c.y * scale;
        q[i][6] = c.z * scale; q[i][7] = c.w * scale;
        sum[i] = 0.0f;
#pragma unroll
        for (int j = 0; j < 8; ++j) o[i][j] = 0.0f;
    }

#pragma unroll
    for (int j = 0; j < 4; ++j) {                 // s = 6j + u
        const int cis = ((node << 2) + j) & 7;    // ci of rows rbase+6j..+5
        const int c1 = ((ch ^ cis) << 2);
        const int c2 = (((ch + 1) ^ cis) << 2);
#pragma unroll
        for (int u = 0; u < 6; ++u) {
            int s = 6 * j + u;
            const float* kr = Ks + (rbase + s) * DD;
            const float* vr = Vs + (rbase + s) * DD;
            float4 k0 = *(const float4*)(kr + c1);
            float4 k1 = *(const float4*)(kr + c2);
            float4 v0 = *(const float4*)(vr + c1);
            float4 v1 = *(const float4*)(vr + c2);
#pragma unroll
            for (int i = 0; i < 3; ++i) {
                float dot = q[i][0] * k0.x;
                dot = fmaf(q[i][1], k0.y, dot);
                dot = fmaf(q[i][2], k0.z, dot);
                dot = fmaf(q[i][3], k0.w, dot);
                dot = fmaf(q[i][4], k1.x, dot);
                dot = fmaf(q[i][5], k1.y, dot);
                dot = fmaf(q[i][6], k1.z, dot);
                dot = fmaf(q[i][7], k1.w, dot);
                float e = (s >= tbase + i) ? __expf(dot) : 0.0f;
                sum[i] += e;
                o[i][0] = fmaf(e, v0.x, o[i][0]);
                o[i][1] = fmaf(e, v0.y, o[i][1]);
                o[i][2] = fmaf(e, v0.z, o[i][2]);
                o[i][3] = fmaf(e, v0.w, o[i][3]);
                o[i][4] = fmaf(e, v1.x, o[i][4]);
                o[i][5] = fmaf(e, v1.y, o[i][5]);
                o[i][6] = fmaf(e, v1.z, o[i][6]);
                o[i][7] = fmaf(e, v1.w, o[i][7]);
            }
        }
    }

#pragma unroll
    for (int i = 0; i < 3; ++i) {
        float inv = 1.0f / sum[i];
        float* orow = Os + (rbase + tbase + i) * DD;
        *(float4*)(orow + qc1) =
            make_float4(o[i][0] * inv, o[i][1] * inv, o[i][2] * inv, o[i][3] * inv);
        *(float4*)(orow + qc2) =
            make_float4(o[i][4] * inv, o[i][5] * inv, o[i][6] * inv, o[i][7] * inv);
    }
}

// ---------------------------------------------------------------------------
// Fused kernel: one CTA per (batch, 4-node tile); 2 CTAs/SM.
// ---------------------------------------------------------------------------
__global__ void __launch_bounds__(NTHREADS, 2)
temporal_attention_fused(const float* __restrict__ X,
                         const float* __restrict__ Wq, const float* __restrict__ bq,
                         const float* __restrict__ Wk, const float* __restrict__ bk,
                         const float* __restrict__ Wv, const float* __restrict__ bv,
                         const float* __restrict__ Wf1, const float* __restrict__ bf1,
                         const float* __restrict__ Wf2, const float* __restrict__ bf2,
                         float* __restrict__ Y) {
    extern __shared__ float smem[];
    float* Xb = smem + XB_OFF;   // X, later attention output O
    float* Qb = smem + QB_OFF;   // Q, later FC1 hidden H
    float* Kb = smem + KB_OFF;
    float* Vb = smem + VB_OFF;
    float* Wp = smem + WP_OFF;

    const int tid = threadIdx.x;
    const int n0 = blockIdx.x * NB;
    const int b = blockIdx.y;

    // Load X tile into swizzled layout; zero-fill out-of-range nodes.
#pragma unroll 2
    for (int i = tid; i < MROWS * 16; i += NTHREADS) {
        int row = i >> 4;
        int f4 = i & 15;
        int node = row / TT;
        int t = row - node * TT;
        int n = n0 + node;
        float4 v = make_float4(0.f, 0.f, 0.f, 0.f);
        if (n < NN)
            v = *(const float4*)(X + ((size_t)(b * TT + t) * NN + n) * DD + f4 * 4);
        *(float4*)(Xb + swz(row, f4)) = v;
    }
    load_weight_pairs(Wp, Wq, tid);
    __syncthreads();

    gemm_to_smem(Xb, Wp, bq, Qb, tid);        // q = relu(X@Wq + bq)
    __syncthreads();
    load_weight_pairs(Wp, Wk, tid);
    __syncthreads();
    gemm_to_smem(Xb, Wp, bk, Kb, tid);        // k
    __syncthreads();
    load_weight_pairs(Wp, Wv, tid);
    __syncthreads();
    gemm_to_smem(Xb, Wp, bv, Vb, tid);        // v
    __syncthreads();

    load_weight_pairs(Wp, Wf1, tid);          // stage Wf1 while attention runs
    attention(Qb, Kb, Vb, Xb, tid);           // O overwrites X buffer
    __syncthreads();

    gemm_to_smem(Xb, Wp, bf1, Qb, tid);       // h = relu(O@Wf1 + bf1) -> Q buffer
    __syncthreads();
    load_weight_pairs(Wp, Wf2, tid);
    __syncthreads();
    gemm_to_global(Qb, Wp, bf2, Y, b, n0, tid);  // y = h@Wf2 + bf2
}

// ---------------------------------------------------------------------------
// kernel_launch: inputs per metadata order:
// 0=X 1=STE(unused) 2=Wq 3=bq 4=Wk 5=bk 6=Wv 7=bv 8=Wf1 9=bf1 10=Wf2 11=bf2
// ---------------------------------------------------------------------------
extern "C" void kernel_launch(void* const* d_in, const int* in_sizes, int n_in,
                              void* d_out, int out_size) {
    const float* X   = (const float*)d_in[0];
    const float* Wq  = (const float*)d_in[2];
    const float* bq  = (const float*)d_in[3];
    const float* Wk  = (const float*)d_in[4];
    const float* bk  = (const float*)d_in[5];
    const float* Wv  = (const float*)d_in[6];
    const float* bv  = (const float*)d_in[7];
    const float* Wf1 = (const float*)d_in[8];
    const float* bf1 = (const float*)d_in[9];
    const float* Wf2 = (const float*)d_in[10];
    const float* bf2 = (const float*)d_in[11];
    float* Y = (float*)d_out;

    cudaFuncSetAttribute(temporal_attention_fused,
                         cudaFuncAttributeMaxDynamicSharedMemorySize, SMEM_BYTES);

    dim3 grid(NTILES, BB);
    temporal_attention_fused<<<grid, NTHREADS, SMEM_BYTES>>>(
        X, Wq, bq, Wk, bk, Wv, bv, Wf1, bf1, Wf2, bf2, Y);
}